// round 6
// baseline (speedup 1.0000x reference)
#include <cuda_runtime.h>
#include <cuda_bf16.h>
#include <cstdint>
#include <cstddef>

// Problem shape (fixed by reference): B=16, T=1024, D=256
#define BB 16
#define TT 1024
#define DD 256

#define TILE 128      // (t,s) tile per CTA
#define KC   32       // K chunk staged through smem
#define LDS_PAD 36    // 32 + 4 pad: bank = (4r+c)%32 -> conflict free, 144B rows stay 16B-aligned

#define C_YX 61.72839506172839f   // 1/(2*0.09^2)
#define C_HW 5.555555555555555f   // 1/(2*0.3^2)

__device__ float g_z2[BB * TT];
__device__ float g_num[BB];
__device__ float g_den[BB];

__device__ __forceinline__ uint32_t f2tf32(float f) {
    uint32_t r;
    asm("cvt.rna.tf32.f32 %0, %1;" : "=r"(r) : "f"(f));
    return r;
}

__device__ __forceinline__ void mma_tf32(float c[4], const uint32_t a[4], const uint32_t b[2]) {
    asm volatile(
        "mma.sync.aligned.m16n8k8.row.col.f32.tf32.tf32.f32 "
        "{%0,%1,%2,%3}, {%4,%5,%6,%7}, {%8,%9}, {%0,%1,%2,%3};"
        : "+f"(c[0]), "+f"(c[1]), "+f"(c[2]), "+f"(c[3])
        : "r"(a[0]), "r"(a[1]), "r"(a[2]), "r"(a[3]), "r"(b[0]), "r"(b[1]));
}

// ---------------------------------------------------------------------------
// Prep: z2[b,t] = sum_d z^2 ; also zero the per-batch accumulators.
// One warp per row. grid = (B*T)/8 blocks of 256 threads.
// ---------------------------------------------------------------------------
__global__ void prep_kernel(const float* __restrict__ z) {
    if (blockIdx.x == 0 && threadIdx.x < BB) {
        g_num[threadIdx.x] = 0.0f;
        g_den[threadIdx.x] = 0.0f;
    }
    int row  = blockIdx.x * 8 + (threadIdx.x >> 5);
    int lane = threadIdx.x & 31;
    const float* p = z + (size_t)row * DD;
    float s = 0.0f;
#pragma unroll
    for (int i = 0; i < 8; i++) {
        float v = p[lane + 32 * i];
        s += v * v;
    }
#pragma unroll
    for (int o = 16; o > 0; o >>= 1) s += __shfl_down_sync(0xFFFFFFFFu, s, o);
    if (lane == 0) g_z2[row] = s;
}

// ---------------------------------------------------------------------------
// Fused: G-tile (tf32 mma) + dT stream + weighted Laplacian reduction.
// grid = (T/TILE, T/TILE, B), block = 256 (8 warps; 2x4 warp grid,
// each warp owns 64x32 of the 128x128 tile => 4x4 m16n8 mma tiles).
// ---------------------------------------------------------------------------
__global__ __launch_bounds__(256, 2)
void fused_kernel(const float* __restrict__ z, const float* __restrict__ dT) {
    __shared__ float As[TILE * LDS_PAD];
    __shared__ float Bs[TILE * LDS_PAD];
    __shared__ float red0[8], red1[8];

    const int b  = blockIdx.z;
    const int t0 = blockIdx.y * TILE;
    const int s0 = blockIdx.x * TILE;

    const float* zb = z + (size_t)b * TT * DD;

    const int tid  = threadIdx.x;
    const int warp = tid >> 5;
    const int lane = tid & 31;
    const int wm   = warp & 1;   // 0..1 : row half (64 rows)
    const int wn   = warp >> 1;  // 0..3 : col quarter (32 cols)
    const int g    = lane >> 2;  // 0..7
    const int tg   = lane & 3;   // 0..3

    float acc[16][4];
#pragma unroll
    for (int i = 0; i < 16; i++)
#pragma unroll
        for (int j = 0; j < 4; j++) acc[i][j] = 0.0f;

    for (int kc = 0; kc < DD; kc += KC) {
        __syncthreads();  // previous stage's reads done
        // Stage A (t rows) and B (s rows): 128x32 floats each = 1024 float4 each.
#pragma unroll
        for (int i = 0; i < 4; i++) {
            int idx = tid + i * 256;
            int r   = idx >> 3;       // row 0..127
            int c4  = idx & 7;        // float4 within 32-float row
            float4 va = *(const float4*)(zb + (size_t)(t0 + r) * DD + kc + c4 * 4);
            *(float4*)(&As[r * LDS_PAD + c4 * 4]) = va;
            float4 vb = *(const float4*)(zb + (size_t)(s0 + r) * DD + kc + c4 * 4);
            *(float4*)(&Bs[r * LDS_PAD + c4 * 4]) = vb;
        }
        __syncthreads();

#pragma unroll
        for (int k8 = 0; k8 < KC; k8 += 8) {
            uint32_t af[4][4], bf[4][2];
            const int ak = k8 + tg;
#pragma unroll
            for (int mi = 0; mi < 4; mi++) {
                const float* p = &As[(wm * 64 + mi * 16 + g) * LDS_PAD + ak];
                af[mi][0] = f2tf32(p[0]);
                af[mi][1] = f2tf32(p[8 * LDS_PAD]);
                af[mi][2] = f2tf32(p[4]);
                af[mi][3] = f2tf32(p[8 * LDS_PAD + 4]);
            }
#pragma unroll
            for (int ni = 0; ni < 4; ni++) {
                const float* p = &Bs[(wn * 32 + ni * 8 + g) * LDS_PAD + ak];
                bf[ni][0] = f2tf32(p[0]);
                bf[ni][1] = f2tf32(p[4]);
            }
#pragma unroll
            for (int mi = 0; mi < 4; mi++)
#pragma unroll
                for (int ni = 0; ni < 4; ni++)
                    mma_tf32(acc[mi * 4 + ni], af[mi], bf[ni]);
        }
    }

    // ---- Epilogue: stream dT tile, form w, accumulate Laplacian energy ----
    float z2t[4][2], z2s[4][2];
#pragma unroll
    for (int mi = 0; mi < 4; mi++) {
        int tt = t0 + wm * 64 + mi * 16 + g;
        z2t[mi][0] = g_z2[b * TT + tt];
        z2t[mi][1] = g_z2[b * TT + tt + 8];
    }
#pragma unroll
    for (int ni = 0; ni < 4; ni++) {
        int ss = s0 + wn * 32 + ni * 8 + 2 * tg;
        z2s[ni][0] = g_z2[b * TT + ss];
        z2s[ni][1] = g_z2[b * TT + ss + 1];
    }

    const float4* dT4 = (const float4*)dT;  // dT is [b][t][s][4] -> float4 index b*T*T + t*T + s
    const size_t base = (size_t)b * TT * TT;

    float sum_w = 0.0f, sum_e = 0.0f;
#pragma unroll
    for (int mi = 0; mi < 4; mi++) {
#pragma unroll
        for (int ni = 0; ni < 4; ni++) {
#pragma unroll
            for (int j = 0; j < 4; j++) {
                int tt = t0 + wm * 64 + mi * 16 + g + ((j >> 1) ? 8 : 0);
                int ss = s0 + wn * 32 + ni * 8 + 2 * tg + (j & 1);
                float4 d4 = __ldg(&dT4[base + (size_t)tt * TT + ss]);
                float e = (d4.x * d4.x + d4.y * d4.y) * C_YX
                        + (d4.z * d4.z + d4.w * d4.w) * C_HW;
                float w = __expf(-e);
                float G = acc[mi * 4 + ni][j];
                sum_w += w;
                sum_e += w * (z2t[mi][j >> 1] + z2s[ni][j & 1] - 2.0f * G);
            }
        }
    }

#pragma unroll
    for (int o = 16; o > 0; o >>= 1) {
        sum_w += __shfl_down_sync(0xFFFFFFFFu, sum_w, o);
        sum_e += __shfl_down_sync(0xFFFFFFFFu, sum_e, o);
    }
    if (lane == 0) { red0[warp] = sum_w; red1[warp] = sum_e; }
    __syncthreads();
    if (tid == 0) {
        float w8 = 0.0f, e8 = 0.0f;
#pragma unroll
        for (int i = 0; i < 8; i++) { w8 += red0[i]; e8 += red1[i]; }
        atomicAdd(&g_den[b], w8);
        atomicAdd(&g_num[b], e8);
    }
}

// ---------------------------------------------------------------------------
// Finalize: mean over batches of num / max(den, 1e-6)
// ---------------------------------------------------------------------------
__global__ void final_kernel(float* __restrict__ out) {
    int lane = threadIdx.x;
    float r = 0.0f;
    if (lane < BB) r = g_num[lane] / fmaxf(g_den[lane], 1e-6f);
#pragma unroll
    for (int o = 16; o > 0; o >>= 1) r += __shfl_down_sync(0xFFFFFFFFu, r, o);
    if (lane == 0) out[0] = r * (1.0f / BB);
}

extern "C" void kernel_launch(void* const* d_in, const int* in_sizes, int n_in,
                              void* d_out, int out_size) {
    const float* z  = (const float*)d_in[0];
    const float* dT = (const float*)d_in[1];
    // Defensive: z has B*T*D = 4.19M elems, gt_dT has B*T*T*4 = 67.1M.
    if (n_in >= 2 && in_sizes[0] > in_sizes[1]) {
        const float* tmp = z; z = dT; dT = tmp;
    }
    (void)out_size;

    prep_kernel<<<(BB * TT) / 8, 256>>>(z);

    dim3 grid(TT / TILE, TT / TILE, BB);
    fused_kernel<<<grid, 256>>>(z, dT);

    final_kernel<<<1, 32>>>((float*)d_out);
}

// round 7
// speedup vs baseline: 1.5120x; 1.5120x over previous
#include <cuda_runtime.h>
#include <cuda_bf16.h>
#include <cstdint>
#include <cstddef>

// Problem shape (fixed by reference): B=16, T=1024, D=256
#define BB 16
#define TT 1024
#define DD 256

#define TILE 128      // (t,s) tile per CTA
#define KC   32       // K chunk staged through smem
#define STRIDE 40     // bf16 units per smem row (32 + 8 pad) -> conflict-free, 16B-aligned rows

#define C_YX 61.72839506172839f   // 1/(2*0.09^2)
#define C_HW 5.555555555555555f   // 1/(2*0.3^2)

__device__ float g_z2[BB * TT];
__device__ float g_num[BB];
__device__ float g_den[BB];
__device__ __nv_bfloat16 g_zb[BB * TT * DD];   // bf16 copy of z (8.4 MB scratch)

__device__ __forceinline__ void cp16(void* dst, const void* src) {
    uint32_t d = (uint32_t)__cvta_generic_to_shared(dst);
    asm volatile("cp.async.cg.shared.global [%0], [%1], 16;\n" :: "r"(d), "l"(src));
}

__device__ __forceinline__ void mma_bf16(float c[4], const uint32_t a[4], const uint32_t b[2]) {
    asm volatile(
        "mma.sync.aligned.m16n8k16.row.col.f32.bf16.bf16.f32 "
        "{%0,%1,%2,%3}, {%4,%5,%6,%7}, {%8,%9}, {%0,%1,%2,%3};"
        : "+f"(c[0]), "+f"(c[1]), "+f"(c[2]), "+f"(c[3])
        : "r"(a[0]), "r"(a[1]), "r"(a[2]), "r"(a[3]), "r"(b[0]), "r"(b[1]));
}

// ---------------------------------------------------------------------------
// Prep: z2[b,t] = sum_d z^2 (fp32), z -> bf16 scratch, zero accumulators.
// One warp per row, float4 loads. grid = (B*T)/8 blocks of 256 threads.
// ---------------------------------------------------------------------------
__global__ void prep_kernel(const float* __restrict__ z) {
    if (blockIdx.x == 0 && threadIdx.x < BB) {
        g_num[threadIdx.x] = 0.0f;
        g_den[threadIdx.x] = 0.0f;
    }
    int row  = blockIdx.x * 8 + (threadIdx.x >> 5);
    int lane = threadIdx.x & 31;
    const float4* p = (const float4*)(z + (size_t)row * DD);
    __nv_bfloat16* ob = g_zb + (size_t)row * DD;
    float s = 0.0f;
#pragma unroll
    for (int i = 0; i < 2; i++) {
        float4 v = p[lane * 2 + i];
        s += v.x * v.x + v.y * v.y + v.z * v.z + v.w * v.w;
        __nv_bfloat162 lo = __floats2bfloat162_rn(v.x, v.y);
        __nv_bfloat162 hi = __floats2bfloat162_rn(v.z, v.w);
        uint2 pk;
        pk.x = *(uint32_t*)&lo;
        pk.y = *(uint32_t*)&hi;
        *(uint2*)(ob + lane * 8 + i * 4) = pk;
    }
#pragma unroll
    for (int o = 16; o > 0; o >>= 1) s += __shfl_down_sync(0xFFFFFFFFu, s, o);
    if (lane == 0) g_z2[row] = s;
}

// ---------------------------------------------------------------------------
// Fused: G-tile (bf16 mma, cp.async double-buffered) + dT stream + reduction.
// grid = (T/TILE, T/TILE, B), block = 256 (8 warps; 2x4 warp grid,
// each warp owns 64x32 of the 128x128 tile => 4x4 m16n8 mma tiles).
// ---------------------------------------------------------------------------
__global__ __launch_bounds__(256, 2)
void fused_kernel(const float* __restrict__ dT) {
    __shared__ __nv_bfloat16 smA[2][TILE * STRIDE];
    __shared__ __nv_bfloat16 smB[2][TILE * STRIDE];
    __shared__ float red0[8], red1[8];

    const int b  = blockIdx.z;
    const int t0 = blockIdx.y * TILE;
    const int s0 = blockIdx.x * TILE;

    const __nv_bfloat16* zbA = g_zb + (size_t)b * TT * DD + (size_t)t0 * DD;
    const __nv_bfloat16* zbB = g_zb + (size_t)b * TT * DD + (size_t)s0 * DD;

    const int tid  = threadIdx.x;
    const int warp = tid >> 5;
    const int lane = tid & 31;
    const int wm   = warp & 1;   // 0..1 : row half (64 rows)
    const int wn   = warp >> 1;  // 0..3 : col quarter (32 cols)
    const int g    = lane >> 2;  // 0..7
    const int tg   = lane & 3;   // 0..3

    // per-thread staging coords: idx in [0,512) covers one 128x32 bf16 tile as 16B units
    const int sr0 = tid >> 2, sc0 = tid & 3;               // i = 0
    const int sr1 = (tid + 256) >> 2, sc1 = (tid + 256) & 3; // i = 1

    float acc[16][4];
#pragma unroll
    for (int i = 0; i < 16; i++)
#pragma unroll
        for (int j = 0; j < 4; j++) acc[i][j] = 0.0f;

    // ---- prologue: stage chunk 0 into buffer 0 ----
    cp16(&smA[0][sr0 * STRIDE + sc0 * 8], zbA + (size_t)sr0 * DD + sc0 * 8);
    cp16(&smB[0][sr0 * STRIDE + sc0 * 8], zbB + (size_t)sr0 * DD + sc0 * 8);
    cp16(&smA[0][sr1 * STRIDE + sc1 * 8], zbA + (size_t)sr1 * DD + sc1 * 8);
    cp16(&smB[0][sr1 * STRIDE + sc1 * 8], zbB + (size_t)sr1 * DD + sc1 * 8);
    asm volatile("cp.async.commit_group;\n" ::);

#pragma unroll
    for (int kci = 0; kci < DD / KC; kci++) {
        if (kci < DD / KC - 1) {
            const int kn = (kci + 1) * KC;
            const int nb = (kci + 1) & 1;
            cp16(&smA[nb][sr0 * STRIDE + sc0 * 8], zbA + (size_t)sr0 * DD + kn + sc0 * 8);
            cp16(&smB[nb][sr0 * STRIDE + sc0 * 8], zbB + (size_t)sr0 * DD + kn + sc0 * 8);
            cp16(&smA[nb][sr1 * STRIDE + sc1 * 8], zbA + (size_t)sr1 * DD + kn + sc1 * 8);
            cp16(&smB[nb][sr1 * STRIDE + sc1 * 8], zbB + (size_t)sr1 * DD + kn + sc1 * 8);
            asm volatile("cp.async.commit_group;\n" ::);
            asm volatile("cp.async.wait_group 1;\n" ::);
        } else {
            asm volatile("cp.async.wait_group 0;\n" ::);
        }
        __syncthreads();

        const __nv_bfloat16* A = smA[kci & 1];
        const __nv_bfloat16* B = smB[kci & 1];
#pragma unroll
        for (int k0 = 0; k0 < KC; k0 += 16) {
            uint32_t af[4][4], bf[4][2];
            const int ak = k0 + 2 * tg;
#pragma unroll
            for (int mi = 0; mi < 4; mi++) {
                const __nv_bfloat16* p = &A[(wm * 64 + mi * 16 + g) * STRIDE + ak];
                af[mi][0] = *(const uint32_t*)(p);
                af[mi][1] = *(const uint32_t*)(p + 8 * STRIDE);
                af[mi][2] = *(const uint32_t*)(p + 8);
                af[mi][3] = *(const uint32_t*)(p + 8 * STRIDE + 8);
            }
#pragma unroll
            for (int ni = 0; ni < 4; ni++) {
                const __nv_bfloat16* p = &B[(wn * 32 + ni * 8 + g) * STRIDE + ak];
                bf[ni][0] = *(const uint32_t*)(p);
                bf[ni][1] = *(const uint32_t*)(p + 8);
            }
#pragma unroll
            for (int mi = 0; mi < 4; mi++)
#pragma unroll
                for (int ni = 0; ni < 4; ni++)
                    mma_bf16(acc[mi * 4 + ni], af[mi], bf[ni]);
        }
        __syncthreads();  // all warps done reading this buffer before it is restaged
    }

    // ---- Epilogue: stream dT tile, form w, accumulate Laplacian energy ----
    float z2t[4][2], z2s[4][2];
#pragma unroll
    for (int mi = 0; mi < 4; mi++) {
        int tt = t0 + wm * 64 + mi * 16 + g;
        z2t[mi][0] = g_z2[b * TT + tt];
        z2t[mi][1] = g_z2[b * TT + tt + 8];
    }
#pragma unroll
    for (int ni = 0; ni < 4; ni++) {
        int ss = s0 + wn * 32 + ni * 8 + 2 * tg;
        z2s[ni][0] = g_z2[b * TT + ss];
        z2s[ni][1] = g_z2[b * TT + ss + 1];
    }

    const float4* dT4 = (const float4*)dT;  // dT is [b][t][s][4] -> float4 index b*T*T + t*T + s
    const size_t base = (size_t)b * TT * TT;

    float sum_w = 0.0f, sum_e = 0.0f;
#pragma unroll
    for (int mi = 0; mi < 4; mi++) {
#pragma unroll
        for (int ni = 0; ni < 4; ni++) {
#pragma unroll
            for (int j = 0; j < 4; j++) {
                int tt = t0 + wm * 64 + mi * 16 + g + ((j >> 1) ? 8 : 0);
                int ss = s0 + wn * 32 + ni * 8 + 2 * tg + (j & 1);
                float4 d4 = __ldg(&dT4[base + (size_t)tt * TT + ss]);
                float e = (d4.x * d4.x + d4.y * d4.y) * C_YX
                        + (d4.z * d4.z + d4.w * d4.w) * C_HW;
                float w = __expf(-e);
                float G = acc[mi * 4 + ni][j];
                sum_w += w;
                sum_e += w * (z2t[mi][j >> 1] + z2s[ni][j & 1] - 2.0f * G);
            }
        }
    }

#pragma unroll
    for (int o = 16; o > 0; o >>= 1) {
        sum_w += __shfl_down_sync(0xFFFFFFFFu, sum_w, o);
        sum_e += __shfl_down_sync(0xFFFFFFFFu, sum_e, o);
    }
    if (lane == 0) { red0[warp] = sum_w; red1[warp] = sum_e; }
    __syncthreads();
    if (tid == 0) {
        float w8 = 0.0f, e8 = 0.0f;
#pragma unroll
        for (int i = 0; i < 8; i++) { w8 += red0[i]; e8 += red1[i]; }
        atomicAdd(&g_den[b], w8);
        atomicAdd(&g_num[b], e8);
    }
}

// ---------------------------------------------------------------------------
// Finalize: mean over batches of num / max(den, 1e-6)
// ---------------------------------------------------------------------------
__global__ void final_kernel(float* __restrict__ out) {
    int lane = threadIdx.x;
    float r = 0.0f;
    if (lane < BB) r = g_num[lane] / fmaxf(g_den[lane], 1e-6f);
#pragma unroll
    for (int o = 16; o > 0; o >>= 1) r += __shfl_down_sync(0xFFFFFFFFu, r, o);
    if (lane == 0) out[0] = r * (1.0f / BB);
}

extern "C" void kernel_launch(void* const* d_in, const int* in_sizes, int n_in,
                              void* d_out, int out_size) {
    const float* z  = (const float*)d_in[0];
    const float* dT = (const float*)d_in[1];
    // Defensive: z has B*T*D = 4.19M elems, gt_dT has B*T*T*4 = 67.1M.
    if (n_in >= 2 && in_sizes[0] > in_sizes[1]) {
        const float* tmp = z; z = dT; dT = tmp;
    }
    (void)out_size;

    prep_kernel<<<(BB * TT) / 8, 256>>>(z);

    dim3 grid(TT / TILE, TT / TILE, BB);
    fused_kernel<<<grid, 256>>>(dT);

    final_kernel<<<1, 32>>>((float*)d_out);
}